// round 1
// baseline (speedup 1.0000x reference)
#include <cuda_runtime.h>
#include <cstdint>

// Problem constants
#define BATCH   512
#define OUTF    1024
#define KDIM    128      // NUM_BLOCKS * LATTICE_DIM
#define NIDX    256      // MAX_INDICES

// Tiling
#define BT      2        // b-rows per CTA
#define OT      512      // o-cols per CTA
#define KB      16       // k per chunk
#define NCHUNK  (KDIM / KB)
#define THREADS 256

// Pre-packed weight indices as bytes (values are < 256 after clip): 1024*128 = 128 KB
__device__ __align__(16) unsigned char g_wpk[OUTF * KDIM];

// Prologue: pack+clip weight_indices int32 -> uint8
__global__ void pack_wgt_kernel(const int* __restrict__ wgt) {
    int t = blockIdx.x * blockDim.x + threadIdx.x;  // 0 .. OUTF*KDIM/4 - 1
    int4 v = ((const int4*)wgt)[t];
    uchar4 p;
    p.x = (unsigned char)min(max(v.x, 0), NIDX - 1);
    p.y = (unsigned char)min(max(v.y, 0), NIDX - 1);
    p.z = (unsigned char)min(max(v.z, 0), NIDX - 1);
    p.w = (unsigned char)min(max(v.w, 0), NIDX - 1);
    ((uchar4*)g_wpk)[t] = p;
}

__global__ __launch_bounds__(THREADS) void lut_kernel(
    const int*   __restrict__ inp,   // [BATCH, KDIM] int32
    const float* __restrict__ lut,   // [256, 256]
    float*       __restrict__ out)   // [BATCH, OUTF]
{
    // Staged LUT rows for this CTA's (BT x KB) (b,k) pairs: 2*16*256 floats = 32 KB
    __shared__ float rows[BT * KB * 256];

    const int tid   = threadIdx.x;
    const int b0    = blockIdx.x * BT;
    const int obase = blockIdx.y * OT + tid;   // first owned o; second is obase+256

    float acc00 = 0.f, acc01 = 0.f;   // b0+0 / b0+1  @ o = obase
    float acc10 = 0.f, acc11 = 0.f;   // b0+0 / b0+1  @ o = obase+256

    for (int c = 0; c < NCHUNK; ++c) {
        const int k0 = c * KB;

        __syncthreads();   // previous chunk's readers done before overwrite

        // ---- Stage BT*KB = 32 LUT rows (1 KB each) into smem, coalesced ----
        float4* rows4 = (float4*)rows;
        #pragma unroll
        for (int i = 0; i < 8; ++i) {
            int f    = tid + i * 256;        // float4 index, 0..2047
            int row  = f >> 6;               // 0..31  == b*KB + k
            int col4 = f & 63;
            int b    = row >> 4;             // row / KB
            int k    = row & (KB - 1);
            int r    = inp[(b0 + b) * KDIM + k0 + k];
            r = min(max(r, 0), NIDX - 1);
            rows4[f] = ((const float4*)(lut + r * 256))[col4];
        }
        __syncthreads();

        // ---- Gather-accumulate from smem rows ----
        #pragma unroll
        for (int oq = 0; oq < 2; ++oq) {
            const int o = obase + oq * 256;
            uint4 w = *(const uint4*)(g_wpk + o * KDIM + k0);  // 16 byte-indices
            unsigned int words[4] = {w.x, w.y, w.z, w.w};
            #pragma unroll
            for (int wi = 0; wi < 4; ++wi) {
                unsigned int wv = words[wi];
                #pragma unroll
                for (int bb = 0; bb < 4; ++bb) {
                    int j = (wv >> (8 * bb)) & 255;
                    int k = wi * 4 + bb;
                    const float* p = rows + k * 256 + j;   // b=0 row block
                    float v0 = p[0];
                    float v1 = p[KB * 256];                // b=1 via immediate offset
                    if (oq == 0) { acc00 += v0; acc01 += v1; }
                    else         { acc10 += v0; acc11 += v1; }
                }
            }
        }
    }

    // Coalesced output writes
    out[(b0 + 0) * OUTF + obase]       = acc00;
    out[(b0 + 1) * OUTF + obase]       = acc01;
    out[(b0 + 0) * OUTF + obase + 256] = acc10;
    out[(b0 + 1) * OUTF + obase + 256] = acc11;
}

extern "C" void kernel_launch(void* const* d_in, const int* in_sizes, int n_in,
                              void* d_out, int out_size) {
    const int*   inp = (const int*)d_in[0];    // input_indices  [512,32,4]
    const int*   wgt = (const int*)d_in[1];    // weight_indices [1024,32,4]
    const float* lut = (const float*)d_in[2];  // lut_table [256,256]
    float* out = (float*)d_out;

    // Pack weight indices to bytes (with clip)
    pack_wgt_kernel<<<(OUTF * KDIM / 4) / 256, 256>>>(wgt);

    // Main gather kernel: grid = (512/2 b-tiles, 1024/512 o-tiles) = 512 CTAs
    dim3 grid(BATCH / BT, OUTF / OT);
    lut_kernel<<<grid, THREADS>>>(inp, lut, out);
}

// round 2
// speedup vs baseline: 1.4865x; 1.4865x over previous
#include <cuda_runtime.h>
#include <cstdint>

// Problem constants
#define BATCH   512
#define OUTF    1024
#define KDIM    128      // NUM_BLOCKS * LATTICE_DIM
#define NIDX    256      // MAX_INDICES

// Tiling for main kernel
#define NSEG    8        // k-segments (grid.y)
#define KSEG    16       // k per segment
#define KCH     4        // k per staging chunk
#define NCH     (KSEG / KCH)
#define BT      32       // b per CTA (== warp width, conflict-free requirement)
#define MTHREADS 1024    // 32 warps: warp w owns o = w*32 .. w*32+31

// Packed weight indices (uint8 after clip): 1024*128 = 128 KB
__device__ __align__(16) unsigned char g_wpk[OUTF * KDIM];
// Per-segment partials, [seg][o][b] (b contiguous for coalesced stores): 16 MB
__device__ float g_part[NSEG][OUTF][BATCH];

// ---------------- prologue: pack+clip weight_indices int32 -> uint8 ----------------
__global__ void pack_wgt_kernel(const int* __restrict__ wgt) {
    int t = blockIdx.x * blockDim.x + threadIdx.x;  // 0 .. OUTF*KDIM/4 - 1
    int4 v = ((const int4*)wgt)[t];
    uchar4 p;
    p.x = (unsigned char)min(max(v.x, 0), NIDX - 1);
    p.y = (unsigned char)min(max(v.y, 0), NIDX - 1);
    p.z = (unsigned char)min(max(v.z, 0), NIDX - 1);
    p.w = (unsigned char)min(max(v.w, 0), NIDX - 1);
    ((uchar4*)g_wpk)[t] = p;
}

// ---------------- main kernel: conflict-free smem gather ----------------
// CTA (btile, seg): b in [btile*32, btile*32+32), k in [seg*16, seg*16+16), all o.
// smem layout: S[kk][b][ j ^ b ]  (kk in 0..KCH-1). Load by lane==b is bank-conflict-free.
__global__ __launch_bounds__(MTHREADS, 1) void lut_main(
    const int*   __restrict__ inp,   // [BATCH, KDIM] int32
    const float* __restrict__ lut)   // [256, 256]
{
    extern __shared__ float S[];     // KCH * 32 * 256 floats = 128 KB

    const int btile = blockIdx.x;    // 0..15
    const int seg   = blockIdx.y;    // 0..7
    const int tid   = threadIdx.x;
    const int wid   = tid >> 5;
    const int lane  = tid & 31;
    const int obase = wid * 32;      // this warp's 32 o's

    // j-bytes for o = obase+lane, k = seg*16 .. seg*16+15 (16 bytes)
    uint4 jw = *(const uint4*)(g_wpk + (obase + lane) * KDIM + seg * KSEG);
    const unsigned lx = lane * 0x01010101u;   // fold lane-XOR into all 4 bytes at once

    float acc[32];
    #pragma unroll
    for (int i = 0; i < 32; ++i) acc[i] = 0.f;

    const float* Sl = S + lane * 256;         // lane == b on the gather side

    #pragma unroll
    for (int cc = 0; cc < NCH; ++cc) {
        __syncthreads();   // previous chunk's readers done before overwrite

        // ---- stage KCH*32 = 128 LUT rows; 4 rows per warp; XOR-swizzled, conflict-free ----
        #pragma unroll
        for (int q = 0; q < 4; ++q) {
            int r  = wid * 4 + q;            // row id 0..127
            int kk = r >> 5;                 // 0..3
            int b  = r & 31;                 // 0..31
            int row = inp[(btile * BT + b) * KDIM + seg * KSEG + cc * KCH + kk];
            row = min(max(row, 0), NIDX - 1);
            const float* src = lut + row * 256;
            float*       dstp = S + (kk * 32 + b) * 256;
            #pragma unroll
            for (int t = 0; t < 8; ++t) {
                int j = t * 32 + lane;       // coalesced 128B LDG; STS bank = (lane^b): perm
                dstp[j ^ b] = src[j];
            }
        }
        __syncthreads();

        // ---- gather: per o, broadcast its 4 j-bytes, 4 conflict-free LDS per o ----
        unsigned wv = (cc == 0) ? jw.x : (cc == 1) ? jw.y : (cc == 2) ? jw.z : jw.w;
        #pragma unroll
        for (int oo = 0; oo < 32; ++oo) {
            unsigned w = __shfl_sync(0xffffffffu, wv, oo) ^ lx;  // bytes = j^lane, kk=0..3
            acc[oo] += Sl[ (w         & 255u)          ];
            acc[oo] += Sl[ ((w >> 8)  & 255u) +  8192  ];
            acc[oo] += Sl[ ((w >> 16) & 255u) + 16384  ];
            acc[oo] += Sl[ ((w >> 24)        ) + 24576 ];
        }
    }

    // partial store: g_part[seg][obase+oo][btile*32+lane], coalesced over lane
    float* dst = &g_part[seg][obase][btile * BT + lane];
    #pragma unroll
    for (int oo = 0; oo < 32; ++oo)
        dst[oo * BATCH] = acc[oo];
}

// ---------------- epilogue: transpose-reduce partials -> out[b][o] ----------------
__global__ void reduce_kernel(float* __restrict__ out) {
    __shared__ float tile[32][33];
    const int o0 = blockIdx.x * 32;
    const int b0 = blockIdx.y * 32;
    const int x  = threadIdx.x & 31;   // b offset (read) / o offset (write)
    const int y  = threadIdx.x >> 5;   // 0..7

    float a[4] = {0.f, 0.f, 0.f, 0.f};
    for (int s = 0; s < NSEG; ++s) {
        #pragma unroll
        for (int i = 0; i < 4; ++i)
            a[i] += g_part[s][o0 + y + 8 * i][b0 + x];   // coalesced over x
    }
    #pragma unroll
    for (int i = 0; i < 4; ++i)
        tile[x][y + 8 * i] = a[i];                        // tile[b_idx][o_idx]
    __syncthreads();
    #pragma unroll
    for (int i = 0; i < 4; ++i)
        out[(b0 + y + 8 * i) * OUTF + o0 + x] = tile[y + 8 * i][x];  // coalesced over x
}

// ---------------- launch ----------------
extern "C" void kernel_launch(void* const* d_in, const int* in_sizes, int n_in,
                              void* d_out, int out_size) {
    const int*   inp = (const int*)d_in[0];    // input_indices  [512,32,4]
    const int*   wgt = (const int*)d_in[1];    // weight_indices [1024,32,4]
    const float* lut = (const float*)d_in[2];  // lut_table [256,256]
    float* out = (float*)d_out;

    pack_wgt_kernel<<<(OUTF * KDIM / 4) / 256, 256>>>(wgt);

    const int smem_bytes = KCH * 32 * 256 * (int)sizeof(float);  // 128 KB
    cudaFuncSetAttribute(lut_main, cudaFuncAttributeMaxDynamicSharedMemorySize, smem_bytes);
    dim3 grid(BATCH / BT, NSEG);
    lut_main<<<grid, MTHREADS, smem_bytes>>>(inp, lut);

    reduce_kernel<<<dim3(OUTF / 32, BATCH / 32), 256>>>(out);
}

// round 3
// speedup vs baseline: 1.7035x; 1.1460x over previous
#include <cuda_runtime.h>
#include <cstdint>

// Problem constants
#define BATCH   512
#define OUTF    1024
#define KDIM    128      // NUM_BLOCKS * LATTICE_DIM
#define NIDX    256      // MAX_INDICES

// Tiling for main kernel
#define NSEG    8        // k-segments (grid.y)
#define KSEG    16       // k per segment
#define KCH     2        // k per staging chunk (per buffer)
#define NCH     (KSEG / KCH)   // 8 chunks
#define BT      32       // b per CTA (== warp width, conflict-free requirement)
#define MTHREADS 1024    // 32 warps: warp w owns o = w*32 .. w*32+31
#define BUF_F   (KCH * 32 * 256)   // floats per buffer = 16384 (64 KB)

// Per-segment partials, [seg][o][b] (b contiguous for coalesced stores): 16 MB
__device__ float g_part[NSEG][OUTF][BATCH];

// ---------------- main kernel: double-buffered conflict-free smem gather ----------------
// CTA (btile, seg): b in [btile*32, btile*32+32), k in [seg*16, seg*16+16), all 1024 o.
// smem: S[buf][kk][b][ j ^ b ]; gather with lane==b is bank-conflict-free; staging STS
// (j = t*32+lane, fixed b) is a lane permutation -> also conflict-free.
__global__ __launch_bounds__(MTHREADS, 1) void lut_main(
    const int*   __restrict__ inp,   // [BATCH, KDIM] int32
    const int*   __restrict__ wgt,   // [OUTF, KDIM]  int32
    const float* __restrict__ lut)   // [256, 256]
{
    extern __shared__ float S[];     // 2 * BUF_F floats = 128 KB

    const int btile = blockIdx.x;    // 0..15
    const int seg   = blockIdx.y;    // 0..7
    const int tid   = threadIdx.x;
    const int wid   = tid >> 5;
    const int lane  = tid & 31;
    const int obase = wid * 32;

    // ---- fused pack: this lane's 16 weight indices (o = obase+lane) as 4 byte-words ----
    const int* wp = wgt + (obase + lane) * KDIM + seg * KSEG;
    unsigned jw0, jw1, jw2, jw3;
    {
        int4 v0 = ((const int4*)wp)[0];
        int4 v1 = ((const int4*)wp)[1];
        int4 v2 = ((const int4*)wp)[2];
        int4 v3 = ((const int4*)wp)[3];
        #define CLP(x) ((unsigned)min(max((x), 0), NIDX - 1))
        jw0 = CLP(v0.x) | (CLP(v0.y) << 8) | (CLP(v0.z) << 16) | (CLP(v0.w) << 24);
        jw1 = CLP(v1.x) | (CLP(v1.y) << 8) | (CLP(v1.z) << 16) | (CLP(v1.w) << 24);
        jw2 = CLP(v2.x) | (CLP(v2.y) << 8) | (CLP(v2.z) << 16) | (CLP(v2.w) << 24);
        jw3 = CLP(v3.x) | (CLP(v3.y) << 8) | (CLP(v3.z) << 16) | (CLP(v3.w) << 24);
        #undef CLP
    }
    const unsigned lx = lane * 0x0101u;   // xor folded into bytes 0,1

    // ---- this warp's staging assignment: 2 rows (kk fixed, b0 and b0+1) ----
    const int kw = wid >> 4;              // kk within chunk: 0 or 1
    const int b0 = (wid & 15) * 2;        // first b
    const int b1 = b0 + 1;
    const int* ip0 = inp + (btile * BT + b0) * KDIM + seg * KSEG + kw;
    const int* ip1 = inp + (btile * BT + b1) * KDIM + seg * KSEG + kw;
    float* drow0base = S + (kw * 32 + b0) * 256;   // + buf*BUF_F at use
    float* drow1base = S + (kw * 32 + b1) * 256;

    float acc[32];
    #pragma unroll
    for (int i = 0; i < 32; ++i) acc[i] = 0.f;

    // ---- prologue: stage chunk 0 into buffer 0 ----
    {
        int r0 = min(max(ip0[0], 0), NIDX - 1);
        int r1 = min(max(ip1[0], 0), NIDX - 1);
        const float* s0 = lut + r0 * 256;
        const float* s1 = lut + r1 * 256;
        #pragma unroll
        for (int t = 0; t < 8; ++t) {
            int j = t * 32 + lane;
            drow0base[j ^ b0] = s0[j];
            drow1base[j ^ b1] = s1[j];
        }
    }
    __syncthreads();

    // ---- pipelined chunks ----
    #pragma unroll 1
    for (int c = 0; c < NCH; ++c) {
        // LDG next chunk into registers (latency hides under the gather below)
        float rg0[8], rg1[8];
        if (c < NCH - 1) {
            int r0 = min(max(ip0[(c + 1) * KCH], 0), NIDX - 1);
            int r1 = min(max(ip1[(c + 1) * KCH], 0), NIDX - 1);
            const float* s0 = lut + r0 * 256;
            const float* s1 = lut + r1 * 256;
            #pragma unroll
            for (int t = 0; t < 8; ++t) {
                rg0[t] = s0[t * 32 + lane];
                rg1[t] = s1[t * 32 + lane];
            }
        }

        // gather chunk c from buffer c&1 (conflict-free: lane == b)
        {
            const float* Sb = S + (c & 1) * BUF_F + lane * 256;
            unsigned word = (c < 2) ? jw0 : (c < 4) ? jw1 : (c < 6) ? jw2 : jw3;
            unsigned wv = word >> (16 * (c & 1));   // bytes 0,1 = the 2 kk's of chunk c
            #pragma unroll
            for (int oo = 0; oo < 32; ++oo) {
                unsigned w = __shfl_sync(0xffffffffu, wv, oo) ^ lx;
                acc[oo] += Sb[w & 255u];
                acc[oo] += Sb[8192 + ((w >> 8) & 255u)];
            }
        }

        // STS next chunk into the other buffer (conflict-free permutation)
        if (c < NCH - 1) {
            float* d0 = drow0base + ((c + 1) & 1) * BUF_F;
            float* d1 = drow1base + ((c + 1) & 1) * BUF_F;
            #pragma unroll
            for (int t = 0; t < 8; ++t) {
                int j = t * 32 + lane;
                d0[j ^ b0] = rg0[t];
                d1[j ^ b1] = rg1[t];
            }
        }
        __syncthreads();
    }

    // partial store: g_part[seg][obase+oo][btile*32+lane], coalesced over lane
    float* dst = &g_part[seg][obase][btile * BT + lane];
    #pragma unroll
    for (int oo = 0; oo < 32; ++oo)
        dst[oo * BATCH] = acc[oo];
}

// ---------------- epilogue: transpose-reduce partials -> out[b][o] ----------------
__global__ void reduce_kernel(float* __restrict__ out) {
    __shared__ float tile[32][33];
    const int o0 = blockIdx.x * 32;
    const int b0 = blockIdx.y * 32;
    const int x  = threadIdx.x & 31;   // b offset (read) / o offset (write)
    const int y  = threadIdx.x >> 5;   // 0..7

    float a[4] = {0.f, 0.f, 0.f, 0.f};
    #pragma unroll 1
    for (int s = 0; s < NSEG; ++s) {
        #pragma unroll
        for (int i = 0; i < 4; ++i)
            a[i] += g_part[s][o0 + y + 8 * i][b0 + x];   // coalesced over x
    }
    #pragma unroll
    for (int i = 0; i < 4; ++i)
        tile[x][y + 8 * i] = a[i];                        // tile[b_idx][o_idx]
    __syncthreads();
    #pragma unroll
    for (int i = 0; i < 4; ++i)
        out[(b0 + y + 8 * i) * OUTF + o0 + x] = tile[y + 8 * i][x];  // coalesced over x
}

// ---------------- launch ----------------
extern "C" void kernel_launch(void* const* d_in, const int* in_sizes, int n_in,
                              void* d_out, int out_size) {
    const int*   inp = (const int*)d_in[0];    // input_indices  [512,32,4]
    const int*   wgt = (const int*)d_in[1];    // weight_indices [1024,32,4]
    const float* lut = (const float*)d_in[2];  // lut_table [256,256]
    float* out = (float*)d_out;

    const int smem_bytes = 2 * BUF_F * (int)sizeof(float);  // 128 KB
    cudaFuncSetAttribute(lut_main, cudaFuncAttributeMaxDynamicSharedMemorySize, smem_bytes);
    dim3 grid(BATCH / BT, NSEG);
    lut_main<<<grid, MTHREADS, smem_bytes>>>(inp, wgt, lut);

    reduce_kernel<<<dim3(OUTF / 32, BATCH / 32), 256>>>(out);
}